// round 4
// baseline (speedup 1.0000x reference)
#include <cuda_runtime.h>

// ---------------- problem constants ----------------
#define HW      4096
#define NPIX    (HW*HW)
#define NPATCH  64
#define K1      31458u   // loop1 continues iff count(v>th) <= 31457  <=>  v_(31458) <= th
#define K2      20972u   // loop2 continues iff count(v>th) >= 20972  <=>  v_(20972) >  th

// value window guaranteed (and verified) to contain both quantiles
#define WLO     0x3F0E0000u   // ~0.5547
#define WHI     0x3F1A0000u   // ~0.6016
#define NW1     768           // level-1 bins of 1024 keys each (span = 0xC0000)
#define W1SHIFT 10

// ---------------- device scratch ----------------
__device__ float        g_blur[NPIX];
__device__ unsigned int g_list[NPIX];            // compacted in-window pixels
__device__ unsigned int g_nlist;
__device__ unsigned int g_whist[NPATCH][NW1];
__device__ unsigned int g_above[NPATCH];         // count(key >= WHI)
__device__ int          g_need [NPATCH];         // fallback flag
__device__ unsigned int g_sub  [NPATCH][2][1024];
__device__ unsigned int g_sel  [NPATCH][4];      // bin1, above1, bin2, above2
__device__ unsigned int g_key  [NPATCH][2];
__device__ float        g_th   [NPATCH];

// ---------------- K0: zero scratch ----------------
__global__ void zero_k() {
    int i = blockIdx.x * 256 + threadIdx.x;
    if (i < NPATCH * NW1)      ((unsigned int*)g_whist)[i] = 0u;
    if (i < NPATCH * 2 * 1024) ((unsigned int*)g_sub)[i]   = 0u;
    if (i < NPATCH) { g_above[i] = 0u; g_need[i] = 0; }
    if (i == 0) g_nlist = 0u;
}

// ---------------- K1: blur + windowed smem histogram + list compaction ----------------
// 128 threads x 4 cols = 512 cols (one patch width), 64 rows per block.
// Per-pixel 25-tap fmaf chain IDENTICAL to the passing version (kw outer, kh inner).
__global__ __launch_bounds__(128) void blur_hist(const float* __restrict__ x,
                                                 const float* __restrict__ bk) {
    __shared__ unsigned int wh[NW1];
    __shared__ unsigned int sred[4];
    for (int i = threadIdx.x; i < NW1; i += 128) wh[i] = 0u;
    __syncthreads();

    const float w  = bk[0];
    const int   c0 = blockIdx.x * 512 + threadIdx.x * 4;
    const int   y0 = blockIdx.y * 64;
    const int   patch = ((y0 >> 9) << 3) + (c0 >> 9);
    const bool  safe = (c0 >= 4) && (c0 <= HW - 9);
    const int   lane = threadIdx.x & 31;
    unsigned int cntAbove = 0;

    for (int y = y0; y < y0 + 64; y++) {
        float f[5][12];
        #pragma unroll
        for (int i = 0; i < 5; i++) {
            int yy = y - 2 + i;
            if (yy < 0 || yy >= HW) {
                #pragma unroll
                for (int j = 0; j < 12; j++) f[i][j] = 0.0f;
            } else if (safe) {
                const float4* p = (const float4*)&x[yy * HW + c0 - 4];
                float4 a = __ldg(p), b = __ldg(p + 1), c = __ldg(p + 2);
                f[i][0]=a.x; f[i][1]=a.y; f[i][2]=a.z;  f[i][3]=a.w;
                f[i][4]=b.x; f[i][5]=b.y; f[i][6]=b.z;  f[i][7]=b.w;
                f[i][8]=c.x; f[i][9]=c.y; f[i][10]=c.z; f[i][11]=c.w;
            } else {
                #pragma unroll
                for (int j = 0; j < 12; j++) {
                    int cc = c0 - 4 + j;
                    f[i][j] = (cc >= 0 && cc < HW) ? __ldg(&x[yy * HW + cc]) : 0.0f;
                }
            }
        }
        float4 o;
        float* op = (float*)&o;
        unsigned int keys[4];
        #pragma unroll
        for (int u = 0; u < 4; u++) {
            float acc = 0.0f;
            #pragma unroll
            for (int j = 0; j < 5; j++)        // kw outer
                #pragma unroll
                for (int i = 0; i < 5; i++)    // kh inner (fastest) — Eigen order
                    acc = fmaf(f[i][u + j + 2], w, acc);
            op[u] = acc;
            keys[u] = __float_as_uint(acc);
        }
        *(float4*)&g_blur[y * HW + c0] = o;

        #pragma unroll
        for (int u = 0; u < 4; u++) {
            unsigned int key = keys[u];
            bool above = key >= WHI;
            bool inwin = (key >= WLO) && (key < WHI);
            cntAbove += above ? 1u : 0u;
            if (inwin) atomicAdd(&wh[(key - WLO) >> W1SHIFT], 1u);
            unsigned int m = __ballot_sync(0xffffffffu, inwin);
            if (m) {
                int leader = __ffs(m) - 1;
                unsigned int base = 0;
                if (lane == leader) base = atomicAdd(&g_nlist, (unsigned)__popc(m));
                base = __shfl_sync(0xffffffffu, base, leader);
                if (inwin) {
                    unsigned int rank = __popc(m & ((1u << lane) - 1u));
                    g_list[base + rank] = ((unsigned int)patch << 20) | (key - WLO);
                }
            }
        }
    }
    // reduce cntAbove per block -> one global atomic
    #pragma unroll
    for (int off = 16; off; off >>= 1)
        cntAbove += __shfl_down_sync(0xffffffffu, cntAbove, off);
    if (lane == 0) sred[threadIdx.x >> 5] = cntAbove;
    __syncthreads();
    if (threadIdx.x == 0)
        atomicAdd(&g_above[patch], sred[0] + sred[1] + sred[2] + sred[3]);
    for (int i = threadIdx.x; i < NW1; i += 128) {
        unsigned int v = wh[i];
        if (v) atomicAdd(&g_whist[patch][i], v);
    }
}

// ---------------- K2: locate level-1 bin for each quantile; verify window ----------------
__global__ __launch_bounds__(1024) void coarse_select_win() {
    __shared__ unsigned int ss[1024];
    const int p = blockIdx.x, t = threadIdx.x;
    unsigned int c = (t < NW1) ? g_whist[p][t] : 0u;
    ss[t] = c;
    __syncthreads();
    for (int off = 1; off < 1024; off <<= 1) {   // inclusive suffix scan
        unsigned int v = (t + off < 1024) ? ss[t + off] : 0u;
        __syncthreads();
        ss[t] += v;
        __syncthreads();
    }
    const unsigned int ga = g_above[p];
    const unsigned int total_in = ss[0];
    unsigned int above = ((t < 1023) ? ss[t + 1] : 0u) + ga;

    if (t == 0)
        g_need[p] = (ga >= K2) || (ga + total_in < K1) ? 1 : 0;

    if (above < K1 && K1 <= above + c) { g_sel[p][0] = (unsigned)t; g_sel[p][1] = above; }
    if (above < K2 && K2 <= above + c) { g_sel[p][2] = (unsigned)t; g_sel[p][3] = above; }
}

// ---------------- K3a: sub-histogram from compacted list ----------------
__global__ __launch_bounds__(256) void refine_hist_list() {
    const unsigned int n = g_nlist;
    for (unsigned int i = blockIdx.x * 256 + threadIdx.x; i < n; i += 256 * 256) {
        unsigned int e = g_list[i];
        unsigned int p = e >> 20, wk = e & 0xFFFFFu, bin = wk >> W1SHIFT;
        if (bin == g_sel[p][0]) atomicAdd(&g_sub[p][0][wk & 1023u], 1u);
        if (bin == g_sel[p][2]) atomicAdd(&g_sub[p][1][wk & 1023u], 1u);
    }
}

// ---------------- K3b: exact float-bit key within the level-1 bin ----------------
__global__ __launch_bounds__(1024) void refine_select() {
    __shared__ unsigned int ss[1024];
    const int p = blockIdx.x, t = threadIdx.x;
    if (g_need[p]) return;

    for (int q = 0; q < 2; q++) {
        const unsigned int bin = g_sel[p][q * 2];
        const unsigned int ab  = g_sel[p][q * 2 + 1];
        const unsigned int r   = (q ? K2 : K1) - ab;

        unsigned int c = g_sub[p][q][t];
        ss[t] = c;
        __syncthreads();
        for (int off = 1; off < 1024; off <<= 1) {
            unsigned int v = (t + off < 1024) ? ss[t + off] : 0u;
            __syncthreads();
            ss[t] += v;
            __syncthreads();
        }
        unsigned int above = (t < 1023) ? ss[t + 1] : 0u;
        if (t == 0) g_key[p][q] = WLO + (bin << W1SHIFT);
        __syncthreads();
        if (above < r && r <= above + c)
            g_key[p][q] = WLO + (bin << W1SHIFT) + (unsigned)t;
        __syncthreads();
    }
}

// ---------------- K3c: gated exact fallback (binary search on key) ----------------
__global__ __launch_bounds__(1024) void fb_exact() {
    const int p = blockIdx.x;
    if (!g_need[p]) return;
    __shared__ unsigned int sred[32];
    __shared__ unsigned int scnt;
    const float* base = g_blur + ((p >> 3) * 512) * HW + (p & 7) * 512;
    const int t = threadIdx.x, lane = t & 31, wid = t >> 5;

    for (int q = 0; q < 2; q++) {
        const unsigned int K = q ? K2 : K1;
        unsigned int lo = 0u, hi = 0x40000000u;   // f(lo)=all>=K, f(hi)=0<K
        while (hi - lo > 1u) {
            unsigned int mid = lo + ((hi - lo) >> 1);
            unsigned int cnt = 0;
            for (int i = t; i < 512 * 512; i += 1024) {
                unsigned int key = __float_as_uint(base[(i >> 9) * HW + (i & 511)]);
                cnt += (key >= mid) ? 1u : 0u;
            }
            #pragma unroll
            for (int off = 16; off; off >>= 1)
                cnt += __shfl_down_sync(0xffffffffu, cnt, off);
            if (lane == 0) sred[wid] = cnt;
            __syncthreads();
            if (t == 0) {
                unsigned int s = 0;
                for (int i = 0; i < 32; i++) s += sred[i];
                scnt = s;
            }
            __syncthreads();
            if (scnt >= K) lo = mid; else hi = mid;
            __syncthreads();
        }
        if (t == 0) g_key[p][q] = lo;
        __syncthreads();
    }
}

// ---------------- K4: sequential threshold walk (bit-faithful) ----------------
__global__ void walk() {
    if (blockIdx.x == 0 && threadIdx.x == 0) {
        float th = 0.5f;
        for (int p = 0; p < NPATCH; p++) {
            float A = __uint_as_float(g_key[p][0]);
            float B = __uint_as_float(g_key[p][1]);
            int g = 0;
            while (A <= th && g < 200000) { th -= 0.0005f; g++; }
            g = 0;
            while (B >  th && g < 200000) { th += 0.0005f; g++; }
            g_th[p] = th;
        }
    }
}

// ---------------- K5: bit-packed binarize + close (dilate5, erode5) ----------------
#define CTW  256
#define CTH  128
#define WPR  10
#define TROWS 136
__global__ __launch_bounds__(256) void close_k(float* __restrict__ out) {
    __shared__ unsigned int A[TROWS][WPR];
    __shared__ unsigned int B[TROWS][WPR];
    __shared__ float sth[NPATCH];
    const int t = threadIdx.x;
    if (t < NPATCH) sth[t] = g_th[t];
    __syncthreads();

    const int gx0 = blockIdx.x * CTW;
    const int gy0 = blockIdx.y * CTH;
    const int lane = t & 31, wid = t >> 5;

    for (int idx = wid; idx < TROWS * WPR; idx += 8) {
        int r = idx / WPR, wc = idx % WPR;
        int gy = gy0 + r - 4;
        int gx = gx0 + (wc - 1) * 32 + lane;
        unsigned int bit = 0;
        if ((unsigned)gy < HW && (unsigned)gx < HW) {
            float bl = g_blur[gy * HW + gx];
            bit = (bl > sth[((gy >> 9) << 3) + (gx >> 9)]) ? 1u : 0u;
        }
        unsigned int word = __ballot_sync(0xffffffffu, bit);
        if (lane == 0) A[r][wc] = word;
    }
    __syncthreads();

    for (int i = t; i < TROWS * WPR; i += 256) {
        int r = i / WPR, wc = i % WPR;
        unsigned int wv = A[r][wc];
        unsigned int lw = wc > 0       ? A[r][wc - 1] : 0u;
        unsigned int rw = wc < WPR - 1 ? A[r][wc + 1] : 0u;
        B[r][wc] = wv | __funnelshift_r(wv, rw, 1) | __funnelshift_r(wv, rw, 2)
                      | __funnelshift_l(lw, wv, 1) | __funnelshift_l(lw, wv, 2);
    }
    __syncthreads();

    for (int i = t; i < TROWS * WPR; i += 256) {
        int r = i / WPR, wc = i % WPR;
        unsigned int d = 0u;
        if (r >= 2 && r < TROWS - 2)
            d = B[r-2][wc] | B[r-1][wc] | B[r][wc] | B[r+1][wc] | B[r+2][wc];
        int gy = gy0 + r - 4;
        bool xout = (wc == 0 && gx0 == 0) || (wc == WPR - 1 && gx0 + CTW == HW);
        if ((unsigned)gy >= HW || xout) d = 0xffffffffu;
        A[r][wc] = d;
    }
    __syncthreads();

    for (int i = t; i < TROWS * WPR; i += 256) {
        int r = i / WPR, wc = i % WPR;
        unsigned int wv = A[r][wc];
        unsigned int lw = wc > 0       ? A[r][wc - 1] : 0xffffffffu;
        unsigned int rw = wc < WPR - 1 ? A[r][wc + 1] : 0xffffffffu;
        B[r][wc] = wv & __funnelshift_r(wv, rw, 1) & __funnelshift_r(wv, rw, 2)
                      & __funnelshift_l(lw, wv, 1) & __funnelshift_l(lw, wv, 2);
    }
    __syncthreads();

    for (int i = t; i < CTH * 8; i += 256) {
        int r = (i >> 3) + 4, wc = (i & 7) + 1;
        unsigned int v = B[r-2][wc] & B[r-1][wc] & B[r][wc] & B[r+1][wc] & B[r+2][wc];
        int gy = gy0 + r - 4;
        int gx = gx0 + (wc - 1) * 32;
        float4* o = (float4*)&out[gy * HW + gx];
        #pragma unroll
        for (int q = 0; q < 8; q++) {
            float4 fv;
            fv.x = (v >> (q * 4 + 0)) & 1u ? 1.0f : 0.0f;
            fv.y = (v >> (q * 4 + 1)) & 1u ? 1.0f : 0.0f;
            fv.z = (v >> (q * 4 + 2)) & 1u ? 1.0f : 0.0f;
            fv.w = (v >> (q * 4 + 3)) & 1u ? 1.0f : 0.0f;
            o[q] = fv;
        }
    }
}

// ---------------- launch ----------------
extern "C" void kernel_launch(void* const* d_in, const int* in_sizes, int n_in,
                              void* d_out, int out_size) {
    const float* x  = (const float*)d_in[0];
    const float* bk = (const float*)d_in[1];
    float* out = (float*)d_out;
    (void)in_sizes; (void)n_in; (void)out_size;

    zero_k<<<(NPATCH * 2 * 1024 + 255) / 256, 256>>>();
    blur_hist<<<dim3(HW / 512, HW / 64), 128>>>(x, bk);
    coarse_select_win<<<NPATCH, 1024>>>();
    refine_hist_list<<<256, 256>>>();
    refine_select<<<NPATCH, 1024>>>();
    fb_exact<<<NPATCH, 1024>>>();
    walk<<<1, 32>>>();
    close_k<<<dim3(HW / CTW, HW / CTH), 256>>>(out);
}

// round 5
// speedup vs baseline: 2.3973x; 2.3973x over previous
#include <cuda_runtime.h>

// ---------------- problem constants ----------------
#define HW      4096
#define NPIX    (HW*HW)
#define NPATCH  64
#define K1      31458u   // loop1 continues iff count(v>th) <= 31457  <=>  v_(31458) <= th
#define K2      20972u   // loop2 continues iff count(v>th) >= 20972  <=>  v_(20972) >  th

// value window (verified per-patch; exact fallback if violated)
#define WLO     0x3F0E0000u   // ~0.5547
#define WHI     0x3F1A0000u   // ~0.6016
#define NW1     768           // level-1 bins of 1024 keys each
#define W1SHIFT 10

// ---------------- device scratch ----------------
__device__ float        g_blur[NPIX];
__device__ unsigned int g_whist[NPATCH][NW1];
__device__ unsigned int g_above[NPATCH];         // count(key >= WHI)
__device__ int          g_need [NPATCH];         // exact-fallback flag
__device__ unsigned int g_sub  [NPATCH][2][1024];
__device__ unsigned int g_sel  [NPATCH][4];      // bin1, above1, bin2, above2
__device__ unsigned int g_key  [NPATCH][2];
__device__ float        g_th   [NPATCH];

// ---------------- K0: zero scratch ----------------
__global__ void zero_k() {
    int i = blockIdx.x * 256 + threadIdx.x;
    if (i < NPATCH * NW1)      ((unsigned int*)g_whist)[i] = 0u;
    if (i < NPATCH * 2 * 1024) ((unsigned int*)g_sub)[i]   = 0u;
    if (i < NPATCH) { g_above[i] = 0u; g_need[i] = 0; }
}

// ---------------- K1: blur (register rolling window) + windowed smem histogram ----------------
// 128 threads x 4 cols = 512 cols (one patch width), 64 rows per block.
// Per-pixel 25-tap fmaf chain IDENTICAL to the passing version (kw outer, kh inner).
__device__ __forceinline__ void load_row(float* dst, const float* __restrict__ x,
                                         int yy, int c0, bool safe) {
    if (yy < 0 || yy >= HW) {
        #pragma unroll
        for (int j = 0; j < 12; j++) dst[j] = 0.0f;
    } else if (safe) {
        const float4* p = (const float4*)&x[yy * HW + c0 - 4];
        float4 a = __ldg(p), b = __ldg(p + 1), c = __ldg(p + 2);
        dst[0]=a.x; dst[1]=a.y; dst[2]=a.z;  dst[3]=a.w;
        dst[4]=b.x; dst[5]=b.y; dst[6]=b.z;  dst[7]=b.w;
        dst[8]=c.x; dst[9]=c.y; dst[10]=c.z; dst[11]=c.w;
    } else {
        #pragma unroll
        for (int j = 0; j < 12; j++) {
            int cc = c0 - 4 + j;
            dst[j] = (cc >= 0 && cc < HW) ? __ldg(&x[yy * HW + cc]) : 0.0f;
        }
    }
}

__global__ __launch_bounds__(128) void blur_hist(const float* __restrict__ x,
                                                 const float* __restrict__ bk) {
    __shared__ unsigned int wh[NW1];
    __shared__ unsigned int sred[4];
    for (int i = threadIdx.x; i < NW1; i += 128) wh[i] = 0u;
    __syncthreads();

    const float w  = bk[0];
    const int   c0 = blockIdx.x * 512 + threadIdx.x * 4;
    const int   y0 = blockIdx.y * 64;
    const int   patch = ((y0 >> 9) << 3) + (c0 >> 9);
    const bool  safe = (c0 >= 4) && (c0 <= HW - 9);
    const int   lane = threadIdx.x & 31;
    unsigned int cntAbove = 0;

    float f[5][12];
    #pragma unroll
    for (int i = 0; i < 4; i++) load_row(f[i], x, y0 - 2 + i, c0, safe);

    for (int y = y0; y < y0 + 64; y++) {
        load_row(f[4], x, y + 2, c0, safe);

        float4 o;
        float* op = (float*)&o;
        #pragma unroll
        for (int u = 0; u < 4; u++) {
            float acc = 0.0f;
            #pragma unroll
            for (int j = 0; j < 5; j++)        // kw outer
                #pragma unroll
                for (int i = 0; i < 5; i++)    // kh inner (fastest) — Eigen order
                    acc = fmaf(f[i][u + j + 2], w, acc);
            op[u] = acc;
            unsigned int key = __float_as_uint(acc);
            cntAbove += (key >= WHI) ? 1u : 0u;
            if (key >= WLO && key < WHI)
                atomicAdd(&wh[(key - WLO) >> W1SHIFT], 1u);
        }
        *(float4*)&g_blur[y * HW + c0] = o;

        #pragma unroll
        for (int i = 0; i < 4; i++)
            #pragma unroll
            for (int j = 0; j < 12; j++)
                f[i][j] = f[i + 1][j];
    }

    #pragma unroll
    for (int off = 16; off; off >>= 1)
        cntAbove += __shfl_down_sync(0xffffffffu, cntAbove, off);
    if (lane == 0) sred[threadIdx.x >> 5] = cntAbove;
    __syncthreads();
    if (threadIdx.x == 0)
        atomicAdd(&g_above[patch], sred[0] + sred[1] + sred[2] + sred[3]);
    for (int i = threadIdx.x; i < NW1; i += 128) {
        unsigned int v = wh[i];
        if (v) atomicAdd(&g_whist[patch][i], v);
    }
}

// ---------------- K2: locate level-1 bin for each quantile; verify window ----------------
__global__ __launch_bounds__(1024) void coarse_select_win() {
    __shared__ unsigned int ss[1024];
    const int p = blockIdx.x, t = threadIdx.x;
    unsigned int c = (t < NW1) ? g_whist[p][t] : 0u;
    ss[t] = c;
    __syncthreads();
    for (int off = 1; off < 1024; off <<= 1) {   // inclusive suffix scan
        unsigned int v = (t + off < 1024) ? ss[t + off] : 0u;
        __syncthreads();
        ss[t] += v;
        __syncthreads();
    }
    const unsigned int ga = g_above[p];
    const unsigned int total_in = ss[0];
    unsigned int above = ((t < 1023) ? ss[t + 1] : 0u) + ga;

    if (t == 0)
        g_need[p] = (ga >= K2) || (ga + total_in < K1) ? 1 : 0;

    if (above < K1 && K1 <= above + c) { g_sel[p][0] = (unsigned)t; g_sel[p][1] = above; }
    if (above < K2 && K2 <= above + c) { g_sel[p][2] = (unsigned)t; g_sel[p][3] = above; }
}

// ---------------- K3a: sub-histogram, full re-read of g_blur (float4, grid-stride) ----------------
__global__ __launch_bounds__(256) void refine_pass() {
    __shared__ unsigned int sbin[NPATCH][2];
    if (threadIdx.x < NPATCH) {
        sbin[threadIdx.x][0] = g_sel[threadIdx.x][0];
        sbin[threadIdx.x][1] = g_sel[threadIdx.x][2];
    }
    __syncthreads();
    const float4* b4 = (const float4*)g_blur;
    const unsigned int n4 = NPIX / 4;
    for (unsigned int i = blockIdx.x * 256 + threadIdx.x; i < n4;
         i += gridDim.x * 256) {
        float4 v = __ldg(&b4[i]);
        int y = i >> 10;
        int p = ((y >> 9) << 3) + ((i & 1023u) >> 7);
        const float* vp = (const float*)&v;
        #pragma unroll
        for (int u = 0; u < 4; u++) {
            unsigned int key = __float_as_uint(vp[u]);
            if (key >= WLO && key < WHI) {
                unsigned int wk  = key - WLO;
                unsigned int bin = wk >> W1SHIFT;
                if (bin == sbin[p][0]) atomicAdd(&g_sub[p][0][wk & 1023u], 1u);
                if (bin == sbin[p][1]) atomicAdd(&g_sub[p][1][wk & 1023u], 1u);
            }
        }
    }
}

// ---------------- K3b: exact float-bit key within the level-1 bin ----------------
__global__ __launch_bounds__(1024) void refine_select() {
    __shared__ unsigned int ss[1024];
    const int p = blockIdx.x, t = threadIdx.x;
    if (g_need[p]) return;

    for (int q = 0; q < 2; q++) {
        const unsigned int bin = g_sel[p][q * 2];
        const unsigned int ab  = g_sel[p][q * 2 + 1];
        const unsigned int r   = (q ? K2 : K1) - ab;

        unsigned int c = g_sub[p][q][t];
        ss[t] = c;
        __syncthreads();
        for (int off = 1; off < 1024; off <<= 1) {
            unsigned int v = (t + off < 1024) ? ss[t + off] : 0u;
            __syncthreads();
            ss[t] += v;
            __syncthreads();
        }
        unsigned int above = (t < 1023) ? ss[t + 1] : 0u;
        if (t == 0) g_key[p][q] = WLO + (bin << W1SHIFT);
        __syncthreads();
        if (above < r && r <= above + c)
            g_key[p][q] = WLO + (bin << W1SHIFT) + (unsigned)t;
        __syncthreads();
    }
}

// ---------------- K3c: gated exact fallback (binary search on key) ----------------
__global__ __launch_bounds__(1024) void fb_exact() {
    const int p = blockIdx.x;
    if (!g_need[p]) return;
    __shared__ unsigned int sred[32];
    __shared__ unsigned int scnt;
    const float* base = g_blur + ((p >> 3) * 512) * HW + (p & 7) * 512;
    const int t = threadIdx.x, lane = t & 31, wid = t >> 5;

    for (int q = 0; q < 2; q++) {
        const unsigned int K = q ? K2 : K1;
        unsigned int lo = 0u, hi = 0x40000000u;
        while (hi - lo > 1u) {
            unsigned int mid = lo + ((hi - lo) >> 1);
            unsigned int cnt = 0;
            for (int i = t; i < 512 * 512; i += 1024) {
                unsigned int key = __float_as_uint(base[(i >> 9) * HW + (i & 511)]);
                cnt += (key >= mid) ? 1u : 0u;
            }
            #pragma unroll
            for (int off = 16; off; off >>= 1)
                cnt += __shfl_down_sync(0xffffffffu, cnt, off);
            if (lane == 0) sred[wid] = cnt;
            __syncthreads();
            if (t == 0) {
                unsigned int s = 0;
                for (int i = 0; i < 32; i++) s += sred[i];
                scnt = s;
            }
            __syncthreads();
            if (scnt >= K) lo = mid; else hi = mid;
            __syncthreads();
        }
        if (t == 0) g_key[p][q] = lo;
        __syncthreads();
    }
}

// ---------------- K4: sequential threshold walk (bit-faithful) ----------------
__global__ void walk() {
    if (blockIdx.x == 0 && threadIdx.x == 0) {
        float th = 0.5f;
        for (int p = 0; p < NPATCH; p++) {
            float A = __uint_as_float(g_key[p][0]);
            float B = __uint_as_float(g_key[p][1]);
            int g = 0;
            while (A <= th && g < 200000) { th -= 0.0005f; g++; }
            g = 0;
            while (B >  th && g < 200000) { th += 0.0005f; g++; }
            g_th[p] = th;
        }
    }
}

// ---------------- K5: bit-packed binarize + close (dilate5, erode5) ----------------
#define CTW  256
#define CTH  128
#define WPR  10
#define TROWS 136
__global__ __launch_bounds__(256) void close_k(float* __restrict__ out) {
    __shared__ unsigned int A[TROWS][WPR];
    __shared__ unsigned int B[TROWS][WPR];
    __shared__ float sth[NPATCH];
    const int t = threadIdx.x;
    if (t < NPATCH) sth[t] = g_th[t];
    __syncthreads();

    const int gx0 = blockIdx.x * CTW;
    const int gy0 = blockIdx.y * CTH;
    const int lane = t & 31, wid = t >> 5;

    for (int idx = wid; idx < TROWS * WPR; idx += 8) {
        int r = idx / WPR, wc = idx % WPR;
        int gy = gy0 + r - 4;
        int gx = gx0 + (wc - 1) * 32 + lane;
        unsigned int bit = 0;
        if ((unsigned)gy < HW && (unsigned)gx < HW) {
            float bl = g_blur[gy * HW + gx];
            bit = (bl > sth[((gy >> 9) << 3) + (gx >> 9)]) ? 1u : 0u;
        }
        unsigned int word = __ballot_sync(0xffffffffu, bit);
        if (lane == 0) A[r][wc] = word;
    }
    __syncthreads();

    for (int i = t; i < TROWS * WPR; i += 256) {
        int r = i / WPR, wc = i % WPR;
        unsigned int wv = A[r][wc];
        unsigned int lw = wc > 0       ? A[r][wc - 1] : 0u;
        unsigned int rw = wc < WPR - 1 ? A[r][wc + 1] : 0u;
        B[r][wc] = wv | __funnelshift_r(wv, rw, 1) | __funnelshift_r(wv, rw, 2)
                      | __funnelshift_l(lw, wv, 1) | __funnelshift_l(lw, wv, 2);
    }
    __syncthreads();

    for (int i = t; i < TROWS * WPR; i += 256) {
        int r = i / WPR, wc = i % WPR;
        unsigned int d = 0u;
        if (r >= 2 && r < TROWS - 2)
            d = B[r-2][wc] | B[r-1][wc] | B[r][wc] | B[r+1][wc] | B[r+2][wc];
        int gy = gy0 + r - 4;
        bool xout = (wc == 0 && gx0 == 0) || (wc == WPR - 1 && gx0 + CTW == HW);
        if ((unsigned)gy >= HW || xout) d = 0xffffffffu;
        A[r][wc] = d;
    }
    __syncthreads();

    for (int i = t; i < TROWS * WPR; i += 256) {
        int r = i / WPR, wc = i % WPR;
        unsigned int wv = A[r][wc];
        unsigned int lw = wc > 0       ? A[r][wc - 1] : 0xffffffffu;
        unsigned int rw = wc < WPR - 1 ? A[r][wc + 1] : 0xffffffffu;
        B[r][wc] = wv & __funnelshift_r(wv, rw, 1) & __funnelshift_r(wv, rw, 2)
                      & __funnelshift_l(lw, wv, 1) & __funnelshift_l(lw, wv, 2);
    }
    __syncthreads();

    for (int i = t; i < CTH * 8; i += 256) {
        int r = (i >> 3) + 4, wc = (i & 7) + 1;
        unsigned int v = B[r-2][wc] & B[r-1][wc] & B[r][wc] & B[r+1][wc] & B[r+2][wc];
        int gy = gy0 + r - 4;
        int gx = gx0 + (wc - 1) * 32;
        float4* o = (float4*)&out[gy * HW + gx];
        #pragma unroll
        for (int q = 0; q < 8; q++) {
            float4 fv;
            fv.x = (v >> (q * 4 + 0)) & 1u ? 1.0f : 0.0f;
            fv.y = (v >> (q * 4 + 1)) & 1u ? 1.0f : 0.0f;
            fv.z = (v >> (q * 4 + 2)) & 1u ? 1.0f : 0.0f;
            fv.w = (v >> (q * 4 + 3)) & 1u ? 1.0f : 0.0f;
            o[q] = fv;
        }
    }
}

// ---------------- launch ----------------
extern "C" void kernel_launch(void* const* d_in, const int* in_sizes, int n_in,
                              void* d_out, int out_size) {
    const float* x  = (const float*)d_in[0];
    const float* bk = (const float*)d_in[1];
    float* out = (float*)d_out;
    (void)in_sizes; (void)n_in; (void)out_size;

    zero_k<<<(NPATCH * 2 * 1024 + 255) / 256, 256>>>();
    blur_hist<<<dim3(HW / 512, HW / 64), 128>>>(x, bk);
    coarse_select_win<<<NPATCH, 1024>>>();
    refine_pass<<<2048, 256>>>();
    refine_select<<<NPATCH, 1024>>>();
    fb_exact<<<NPATCH, 1024>>>();
    walk<<<1, 32>>>();
    close_k<<<dim3(HW / CTW, HW / CTH), 256>>>(out);
}

// round 6
// speedup vs baseline: 2.6378x; 1.1003x over previous
#include <cuda_runtime.h>

// ---------------- problem constants ----------------
#define HW      4096
#define NPIX    (HW*HW)
#define NPATCH  64
#define K1      31458u   // loop1 continues iff count(v>th) <= 31457  <=>  v_(31458) <= th
#define K2      20972u   // loop2 continues iff count(v>th) >= 20972  <=>  v_(20972) >  th

// value window (verified per-patch; exact fallback if violated)
#define WLO     0x3F0E0000u   // ~0.5547
#define WHI     0x3F1A0000u   // ~0.6016
#define NW1     768           // level-1 bins of 1024 keys each
#define W1SHIFT 10

#define RPB     32            // rows per blur block (occupancy lever)

// ---------------- device scratch ----------------
__device__ float        g_blur[NPIX];
__device__ unsigned int g_whist[NPATCH][NW1];
__device__ unsigned int g_above[NPATCH];         // count(key >= WHI)
__device__ int          g_need [NPATCH];         // exact-fallback flag
__device__ unsigned int g_sub  [NPATCH][2][1024];
__device__ unsigned int g_sel  [NPATCH][4];      // bin1, above1, bin2, above2
__device__ unsigned int g_key  [NPATCH][2];
__device__ float        g_th   [NPATCH];

// ---------------- K0: zero scratch ----------------
__global__ void zero_k() {
    int i = blockIdx.x * 256 + threadIdx.x;
    if (i < NPATCH * NW1)      ((unsigned int*)g_whist)[i] = 0u;
    if (i < NPATCH * 2 * 1024) ((unsigned int*)g_sub)[i]   = 0u;
    if (i < NPATCH) { g_above[i] = 0u; g_need[i] = 0; }
}

// ---------------- K1: blur (register rolling window) + windowed smem histogram ----------------
// 128 threads x 4 cols = 512 cols (one patch width), RPB rows per block.
// Per-pixel 25-tap fmaf chain IDENTICAL to the passing version (kw outer, kh inner).
__device__ __forceinline__ void load_row(float* dst, const float* __restrict__ x,
                                         int yy, int c0, bool safe) {
    if (yy < 0 || yy >= HW) {
        #pragma unroll
        for (int j = 0; j < 12; j++) dst[j] = 0.0f;
    } else if (safe) {
        const float4* p = (const float4*)&x[yy * HW + c0 - 4];
        float4 a = __ldg(p), b = __ldg(p + 1), c = __ldg(p + 2);
        dst[0]=a.x; dst[1]=a.y; dst[2]=a.z;  dst[3]=a.w;
        dst[4]=b.x; dst[5]=b.y; dst[6]=b.z;  dst[7]=b.w;
        dst[8]=c.x; dst[9]=c.y; dst[10]=c.z; dst[11]=c.w;
    } else {
        #pragma unroll
        for (int j = 0; j < 12; j++) {
            int cc = c0 - 4 + j;
            dst[j] = (cc >= 0 && cc < HW) ? __ldg(&x[yy * HW + cc]) : 0.0f;
        }
    }
}

__global__ __launch_bounds__(128) void blur_hist(const float* __restrict__ x,
                                                 const float* __restrict__ bk) {
    __shared__ unsigned int wh[NW1];
    __shared__ unsigned int sred[4];
    for (int i = threadIdx.x; i < NW1; i += 128) wh[i] = 0u;
    __syncthreads();

    const float w  = bk[0];
    const int   c0 = blockIdx.x * 512 + threadIdx.x * 4;
    const int   y0 = blockIdx.y * RPB;
    const int   patch = ((y0 >> 9) << 3) + (c0 >> 9);
    const bool  safe = (c0 >= 4) && (c0 <= HW - 9);
    const int   lane = threadIdx.x & 31;
    unsigned int cntAbove = 0;

    float f[5][12];
    #pragma unroll
    for (int i = 0; i < 4; i++) load_row(f[i], x, y0 - 2 + i, c0, safe);

    for (int y = y0; y < y0 + RPB; y++) {
        load_row(f[4], x, y + 2, c0, safe);

        float4 o;
        float* op = (float*)&o;
        #pragma unroll
        for (int u = 0; u < 4; u++) {
            float acc = 0.0f;
            #pragma unroll
            for (int j = 0; j < 5; j++)        // kw outer
                #pragma unroll
                for (int i = 0; i < 5; i++)    // kh inner (fastest) — Eigen order
                    acc = fmaf(f[i][u + j + 2], w, acc);
            op[u] = acc;
            unsigned int key = __float_as_uint(acc);
            cntAbove += (key >= WHI) ? 1u : 0u;
            if (key >= WLO && key < WHI)
                atomicAdd(&wh[(key - WLO) >> W1SHIFT], 1u);
        }
        *(float4*)&g_blur[y * HW + c0] = o;

        #pragma unroll
        for (int i = 0; i < 4; i++)
            #pragma unroll
            for (int j = 0; j < 12; j++)
                f[i][j] = f[i + 1][j];
    }

    #pragma unroll
    for (int off = 16; off; off >>= 1)
        cntAbove += __shfl_down_sync(0xffffffffu, cntAbove, off);
    if (lane == 0) sred[threadIdx.x >> 5] = cntAbove;
    __syncthreads();
    if (threadIdx.x == 0)
        atomicAdd(&g_above[patch], sred[0] + sred[1] + sred[2] + sred[3]);
    for (int i = threadIdx.x; i < NW1; i += 128) {
        unsigned int v = wh[i];
        if (v) atomicAdd(&g_whist[patch][i], v);
    }
}

// ---------------- K2: locate level-1 bin for each quantile; verify window ----------------
__global__ __launch_bounds__(1024) void coarse_select_win() {
    __shared__ unsigned int ss[1024];
    const int p = blockIdx.x, t = threadIdx.x;
    unsigned int c = (t < NW1) ? g_whist[p][t] : 0u;
    ss[t] = c;
    __syncthreads();
    for (int off = 1; off < 1024; off <<= 1) {   // inclusive suffix scan
        unsigned int v = (t + off < 1024) ? ss[t + off] : 0u;
        __syncthreads();
        ss[t] += v;
        __syncthreads();
    }
    const unsigned int ga = g_above[p];
    const unsigned int total_in = ss[0];
    unsigned int above = ((t < 1023) ? ss[t + 1] : 0u) + ga;

    if (t == 0)
        g_need[p] = (ga >= K2) || (ga + total_in < K1) ? 1 : 0;

    if (above < K1 && K1 <= above + c) { g_sel[p][0] = (unsigned)t; g_sel[p][1] = above; }
    if (above < K2 && K2 <= above + c) { g_sel[p][2] = (unsigned)t; g_sel[p][3] = above; }
}

// ---------------- K3a: sub-histogram, full re-read of g_blur (float4, grid-stride) ----------------
__global__ __launch_bounds__(256) void refine_pass() {
    __shared__ unsigned int sbin[NPATCH][2];
    if (threadIdx.x < NPATCH) {
        sbin[threadIdx.x][0] = g_sel[threadIdx.x][0];
        sbin[threadIdx.x][1] = g_sel[threadIdx.x][2];
    }
    __syncthreads();
    const float4* b4 = (const float4*)g_blur;
    const unsigned int n4 = NPIX / 4;
    for (unsigned int i = blockIdx.x * 256 + threadIdx.x; i < n4;
         i += gridDim.x * 256) {
        float4 v = __ldg(&b4[i]);
        int y = i >> 10;
        int p = ((y >> 9) << 3) + ((i & 1023u) >> 7);
        const float* vp = (const float*)&v;
        #pragma unroll
        for (int u = 0; u < 4; u++) {
            unsigned int key = __float_as_uint(vp[u]);
            if (key >= WLO && key < WHI) {
                unsigned int wk  = key - WLO;
                unsigned int bin = wk >> W1SHIFT;
                if (bin == sbin[p][0]) atomicAdd(&g_sub[p][0][wk & 1023u], 1u);
                if (bin == sbin[p][1]) atomicAdd(&g_sub[p][1][wk & 1023u], 1u);
            }
        }
    }
}

// ---------------- K3b: exact float-bit key within the level-1 bin ----------------
__global__ __launch_bounds__(1024) void refine_select() {
    __shared__ unsigned int ss[1024];
    const int p = blockIdx.x, t = threadIdx.x;
    if (g_need[p]) return;

    for (int q = 0; q < 2; q++) {
        const unsigned int bin = g_sel[p][q * 2];
        const unsigned int ab  = g_sel[p][q * 2 + 1];
        const unsigned int r   = (q ? K2 : K1) - ab;

        unsigned int c = g_sub[p][q][t];
        ss[t] = c;
        __syncthreads();
        for (int off = 1; off < 1024; off <<= 1) {
            unsigned int v = (t + off < 1024) ? ss[t + off] : 0u;
            __syncthreads();
            ss[t] += v;
            __syncthreads();
        }
        unsigned int above = (t < 1023) ? ss[t + 1] : 0u;
        if (t == 0) g_key[p][q] = WLO + (bin << W1SHIFT);
        __syncthreads();
        if (above < r && r <= above + c)
            g_key[p][q] = WLO + (bin << W1SHIFT) + (unsigned)t;
        __syncthreads();
    }
}

// ---------------- K3c: gated exact fallback (binary search on key) ----------------
__global__ __launch_bounds__(1024) void fb_exact() {
    const int p = blockIdx.x;
    if (!g_need[p]) return;
    __shared__ unsigned int sred[32];
    __shared__ unsigned int scnt;
    const float* base = g_blur + ((p >> 3) * 512) * HW + (p & 7) * 512;
    const int t = threadIdx.x, lane = t & 31, wid = t >> 5;

    for (int q = 0; q < 2; q++) {
        const unsigned int K = q ? K2 : K1;
        unsigned int lo = 0u, hi = 0x40000000u;
        while (hi - lo > 1u) {
            unsigned int mid = lo + ((hi - lo) >> 1);
            unsigned int cnt = 0;
            for (int i = t; i < 512 * 512; i += 1024) {
                unsigned int key = __float_as_uint(base[(i >> 9) * HW + (i & 511)]);
                cnt += (key >= mid) ? 1u : 0u;
            }
            #pragma unroll
            for (int off = 16; off; off >>= 1)
                cnt += __shfl_down_sync(0xffffffffu, cnt, off);
            if (lane == 0) sred[wid] = cnt;
            __syncthreads();
            if (t == 0) {
                unsigned int s = 0;
                for (int i = 0; i < 32; i++) s += sred[i];
                scnt = s;
            }
            __syncthreads();
            if (scnt >= K) lo = mid; else hi = mid;
            __syncthreads();
        }
        if (t == 0) g_key[p][q] = lo;
        __syncthreads();
    }
}

// ---------------- K4: sequential threshold walk (bit-faithful) ----------------
__global__ void walk() {
    if (blockIdx.x == 0 && threadIdx.x == 0) {
        float th = 0.5f;
        for (int p = 0; p < NPATCH; p++) {
            float A = __uint_as_float(g_key[p][0]);
            float B = __uint_as_float(g_key[p][1]);
            int g = 0;
            while (A <= th && g < 200000) { th -= 0.0005f; g++; }
            g = 0;
            while (B >  th && g < 200000) { th += 0.0005f; g++; }
            g_th[p] = th;
        }
    }
}

// ---------------- K5: bit-packed binarize + close (dilate5, erode5) ----------------
#define CTW  256
#define CTH  128
#define WPR  10
#define TROWS 136
__global__ __launch_bounds__(256) void close_k(float* __restrict__ out) {
    __shared__ unsigned int A[TROWS][WPR];
    __shared__ unsigned int B[TROWS][WPR];
    __shared__ float sth[NPATCH];
    const int t = threadIdx.x;
    if (t < NPATCH) sth[t] = g_th[t];
    __syncthreads();

    const int gx0 = blockIdx.x * CTW;
    const int gy0 = blockIdx.y * CTH;
    const int lane = t & 31, wid = t >> 5;

    for (int idx = wid; idx < TROWS * WPR; idx += 8) {
        int r = idx / WPR, wc = idx % WPR;
        int gy = gy0 + r - 4;
        int gx = gx0 + (wc - 1) * 32 + lane;
        unsigned int bit = 0;
        if ((unsigned)gy < HW && (unsigned)gx < HW) {
            float bl = g_blur[gy * HW + gx];
            bit = (bl > sth[((gy >> 9) << 3) + (gx >> 9)]) ? 1u : 0u;
        }
        unsigned int word = __ballot_sync(0xffffffffu, bit);
        if (lane == 0) A[r][wc] = word;
    }
    __syncthreads();

    for (int i = t; i < TROWS * WPR; i += 256) {
        int r = i / WPR, wc = i % WPR;
        unsigned int wv = A[r][wc];
        unsigned int lw = wc > 0       ? A[r][wc - 1] : 0u;
        unsigned int rw = wc < WPR - 1 ? A[r][wc + 1] : 0u;
        B[r][wc] = wv | __funnelshift_r(wv, rw, 1) | __funnelshift_r(wv, rw, 2)
                      | __funnelshift_l(lw, wv, 1) | __funnelshift_l(lw, wv, 2);
    }
    __syncthreads();

    for (int i = t; i < TROWS * WPR; i += 256) {
        int r = i / WPR, wc = i % WPR;
        unsigned int d = 0u;
        if (r >= 2 && r < TROWS - 2)
            d = B[r-2][wc] | B[r-1][wc] | B[r][wc] | B[r+1][wc] | B[r+2][wc];
        int gy = gy0 + r - 4;
        bool xout = (wc == 0 && gx0 == 0) || (wc == WPR - 1 && gx0 + CTW == HW);
        if ((unsigned)gy >= HW || xout) d = 0xffffffffu;
        A[r][wc] = d;
    }
    __syncthreads();

    for (int i = t; i < TROWS * WPR; i += 256) {
        int r = i / WPR, wc = i % WPR;
        unsigned int wv = A[r][wc];
        unsigned int lw = wc > 0       ? A[r][wc - 1] : 0xffffffffu;
        unsigned int rw = wc < WPR - 1 ? A[r][wc + 1] : 0xffffffffu;
        B[r][wc] = wv & __funnelshift_r(wv, rw, 1) & __funnelshift_r(wv, rw, 2)
                      & __funnelshift_l(lw, wv, 1) & __funnelshift_l(lw, wv, 2);
    }
    __syncthreads();

    for (int i = t; i < CTH * 8; i += 256) {
        int r = (i >> 3) + 4, wc = (i & 7) + 1;
        unsigned int v = B[r-2][wc] & B[r-1][wc] & B[r][wc] & B[r+1][wc] & B[r+2][wc];
        int gy = gy0 + r - 4;
        int gx = gx0 + (wc - 1) * 32;
        float4* o = (float4*)&out[gy * HW + gx];
        #pragma unroll
        for (int q = 0; q < 8; q++) {
            float4 fv;
            fv.x = (v >> (q * 4 + 0)) & 1u ? 1.0f : 0.0f;
            fv.y = (v >> (q * 4 + 1)) & 1u ? 1.0f : 0.0f;
            fv.z = (v >> (q * 4 + 2)) & 1u ? 1.0f : 0.0f;
            fv.w = (v >> (q * 4 + 3)) & 1u ? 1.0f : 0.0f;
            o[q] = fv;
        }
    }
}

// ---------------- launch ----------------
extern "C" void kernel_launch(void* const* d_in, const int* in_sizes, int n_in,
                              void* d_out, int out_size) {
    const float* x  = (const float*)d_in[0];
    const float* bk = (const float*)d_in[1];
    float* out = (float*)d_out;
    (void)in_sizes; (void)n_in; (void)out_size;

    zero_k<<<(NPATCH * 2 * 1024 + 255) / 256, 256>>>();
    blur_hist<<<dim3(HW / 512, HW / RPB), 128>>>(x, bk);
    coarse_select_win<<<NPATCH, 1024>>>();
    refine_pass<<<2048, 256>>>();
    refine_select<<<NPATCH, 1024>>>();
    fb_exact<<<NPATCH, 1024>>>();
    walk<<<1, 32>>>();
    close_k<<<dim3(HW / CTW, HW / CTH), 256>>>(out);
}